// round 1
// baseline (speedup 1.0000x reference)
#include <cuda_runtime.h>
#include <math.h>

#define TSEQ 500
#define BATCH 512
#define NS 64
#define NO 64
#define NI 32
#define SRD 68   // smem row stride (floats): 16B-aligned, kills stride-64 bank conflicts

// Precomputed constants (filled by akf_prep each launch; deterministic)
__device__ float g_Ht[NS * NO];   // g_Ht[k*64+c] = H[c][k]  (transposed H)
__device__ float g_q[NS];         // exp(logsigma)^2
__device__ float g_r[NO];         // exp(logdelta)^2

__global__ void akf_prep(const float* __restrict__ H,
                         const float* __restrict__ lsig,
                         const float* __restrict__ ldel) {
    int t = blockIdx.x * blockDim.x + threadIdx.x;
    if (t < NS * NO) {
        int c = t & 63, k = t >> 6;
        g_Ht[k * NO + c] = H[c * NS + k];
    }
    if (t < NS) { float e = expf(lsig[t]); g_q[t] = e * e; }
    if (t < NO) { float e = expf(ldel[t]); g_r[t] = e * e; }
}

#define OUTER4(ar, as, bv) { ar[0] += (as)*(bv).x; ar[1] += (as)*(bv).y; \
                             ar[2] += (as)*(bv).z; ar[3] += (as)*(bv).w; }
#define DOT4(acc, u, v) { acc += (u).x*(v).x + (u).y*(v).y + (u).z*(v).z + (u).w*(v).w; }

__global__ void __launch_bounds__(256, 4)
akf_main(const float* __restrict__ ext, const float* __restrict__ obs,
         const float* __restrict__ mu0, const float* __restrict__ sg0,
         const float* __restrict__ Bm, float* __restrict__ out)
{
    extern __shared__ float smf[];
    float* Mc = smf;                  // cov / cov_pred, 64 x SRD (kept exactly symmetric)
    float* T  = Mc + 64 * SRD;        // T = M*Ht, then U~ ; 65 rows (row 64 = innov/z)
    float* S  = T + 65 * SRD;         // S, then L (unit-lower, scaled) + D on diag
    float* mu   = S + 64 * SRD;       // 64
    float* mup  = mu + 64;            // 64
    float* uv   = mup + 64;           // 32
    float* rinv = uv + 32;            // 64  (1/d_j)
    float* srin = rinv + 64;          // 64  (1/sqrt(d_j))

    const int b   = blockIdx.x;
    const int tid = threadIdx.x;
    const int r0  = (tid >> 4) << 2;  // 4x4 output tile coords
    const int c0  = (tid & 15) << 2;

    float* outmu = out;
    float* outls = out + (size_t)TSEQ * BATCH * NS;

    // ---- init: cov = diag(sigma0^2), emit t=0 outputs ----
    for (int idx = tid; idx < 64 * 64; idx += 256)
        Mc[(idx >> 6) * SRD + (idx & 63)] = 0.0f;
    __syncthreads();
    if (tid < NS) {
        float m0 = mu0[b * NS + tid];
        float s0 = sg0[b * NS + tid];
        mu[tid] = m0;
        Mc[tid * SRD + tid] = s0 * s0;
        outmu[b * NS + tid] = m0;
        outls[b * NS + tid] = logf(s0);
    }
    __syncthreads();

    for (int t = 1; t < TSEQ; ++t) {
        // ---- A: load u,y ; cov_pred = cov + diag(q) ----
        if (tid < NI) uv[tid] = ext[((size_t)(t - 1) * BATCH + b) * NI + tid];
        if (tid < NO) T[64 * SRD + tid] = obs[((size_t)t * BATCH + b) * NO + tid];
        if (tid < NS) Mc[tid * SRD + tid] += g_q[tid];
        __syncthreads();

        // ---- B: mu_pred = mu + B u ; GEMM1: T = M * Ht ----
        if (tid < NS) {
            float s = mu[tid];
            const float* Br = Bm + tid * NI;
            #pragma unroll 8
            for (int j = 0; j < NI; ++j) s += Br[j] * uv[j];
            mup[tid] = s;
        }
        {
            float acc[4][4] = {};
            #pragma unroll 1
            for (int k0 = 0; k0 < 64; k0 += 4) {
                float4 A0 = *(const float4*)&Mc[(r0 + 0) * SRD + k0];
                float4 A1 = *(const float4*)&Mc[(r0 + 1) * SRD + k0];
                float4 A2 = *(const float4*)&Mc[(r0 + 2) * SRD + k0];
                float4 A3 = *(const float4*)&Mc[(r0 + 3) * SRD + k0];
                float4 B0 = __ldg((const float4*)&g_Ht[(k0 + 0) * NO + c0]);
                float4 B1 = __ldg((const float4*)&g_Ht[(k0 + 1) * NO + c0]);
                float4 B2 = __ldg((const float4*)&g_Ht[(k0 + 2) * NO + c0]);
                float4 B3 = __ldg((const float4*)&g_Ht[(k0 + 3) * NO + c0]);
                OUTER4(acc[0], A0.x, B0); OUTER4(acc[0], A0.y, B1); OUTER4(acc[0], A0.z, B2); OUTER4(acc[0], A0.w, B3);
                OUTER4(acc[1], A1.x, B0); OUTER4(acc[1], A1.y, B1); OUTER4(acc[1], A1.z, B2); OUTER4(acc[1], A1.w, B3);
                OUTER4(acc[2], A2.x, B0); OUTER4(acc[2], A2.y, B1); OUTER4(acc[2], A2.z, B2); OUTER4(acc[2], A2.w, B3);
                OUTER4(acc[3], A3.x, B0); OUTER4(acc[3], A3.y, B1); OUTER4(acc[3], A3.z, B2); OUTER4(acc[3], A3.w, B3);
            }
            #pragma unroll
            for (int i = 0; i < 4; ++i)
                *(float4*)&T[(r0 + i) * SRD + c0] =
                    make_float4(acc[i][0], acc[i][1], acc[i][2], acc[i][3]);
        }
        __syncthreads();

        // ---- C: innov -> T row 64 ; GEMM2: S = Ht^T * T + diag(r) ----
        if (tid < NO) {
            float s = T[64 * SRD + tid];       // y
            #pragma unroll 8
            for (int k = 0; k < NS; ++k) s -= g_Ht[k * NO + tid] * mup[k];
            T[64 * SRD + tid] = s;
        }
        {
            float acc[4][4] = {};
            #pragma unroll 1
            for (int k = 0; k < 64; k += 2) {
                float4 a0 = __ldg((const float4*)&g_Ht[k * NO + r0]);
                float4 b0 = *(const float4*)&T[k * SRD + c0];
                OUTER4(acc[0], a0.x, b0); OUTER4(acc[1], a0.y, b0);
                OUTER4(acc[2], a0.z, b0); OUTER4(acc[3], a0.w, b0);
                float4 a1 = __ldg((const float4*)&g_Ht[(k + 1) * NO + r0]);
                float4 b1 = *(const float4*)&T[(k + 1) * SRD + c0];
                OUTER4(acc[0], a1.x, b1); OUTER4(acc[1], a1.y, b1);
                OUTER4(acc[2], a1.z, b1); OUTER4(acc[3], a1.w, b1);
            }
            #pragma unroll
            for (int i = 0; i < 4; ++i)
                #pragma unroll
                for (int j = 0; j < 4; ++j) {
                    int a = r0 + i, c = c0 + j;
                    float v = acc[i][j];
                    if (a == c) v += g_r[a];
                    S[a * SRD + c] = v;
                }
        }
        __syncthreads();

        // ---- D: LDL^T factorization of S (right-looking, 1 sync per column) ----
        {
            const int di = tid >> 4, dk = tid & 15;
            #pragma unroll 1
            for (int j = 0; j < 64; ++j) {
                float d  = S[j * SRD + j];
                float rv = __fdividef(1.0f, d);
                if (tid == 0) { rinv[j] = rv; srin[j] = rsqrtf(d); }
                #pragma unroll
                for (int ib = 0; ib < 4; ++ib) {
                    int i = j + 1 + di + (ib << 4);
                    if (i < 64) {
                        float lij = S[i * SRD + j] * rv;
                        #pragma unroll
                        for (int kb = 0; kb < 4; ++kb) {
                            int k = j + 1 + dk + (kb << 4);
                            if (k <= i) S[i * SRD + k] -= lij * S[k * SRD + j];
                        }
                    }
                }
                __syncthreads();
            }
            // scale strict lower triangle: L[i][k] = S[i][k] / d_k
            for (int idx = tid; idx < 64 * 64; idx += 256) {
                int i = idx >> 6, k = idx & 63;
                if (k < i) S[i * SRD + k] *= rinv[k];
            }
        }
        __syncthreads();

        // ---- E: blocked forward substitution (unit L), 65 RHS rows in T ----
        #pragma unroll 1
        for (int blk = 0; blk < 4; ++blk) {
            const int i0 = blk << 4;
            if (blk > 0) {
                for (int o = tid; o < 65 * 16; o += 256) {
                    int j = o >> 4;
                    int i = i0 + (o & 15);
                    const float* Lr = &S[i * SRD];
                    float* Tr = &T[j * SRD];
                    float s = 0.0f;
                    #pragma unroll 8
                    for (int k = 0; k < i0; ++k) s += Lr[k] * Tr[k];
                    Tr[i] -= s;
                }
            }
            __syncthreads();
            #pragma unroll 1
            for (int ii = 1; ii < 16; ++ii) {
                const int i = i0 + ii;
                if (tid < 65) {
                    const float* Lr = &S[i * SRD];
                    float* Tr = &T[tid * SRD];
                    float s = 0.0f;
                    for (int k = i0; k < i; ++k) s += Lr[k] * Tr[k];
                    Tr[i] -= s;
                }
                __syncthreads();
            }
        }

        // ---- F: scale columns by 1/sqrt(d): U~ = D^{-1/2} U (rows 0..64) ----
        for (int idx = tid; idx < 65 * 64; idx += 256) {
            int j = idx >> 6, i = idx & 63;
            T[j * SRD + i] *= srin[i];
        }
        __syncthreads();

        // ---- G: mu_post = mu_pred + U~^T z~ ; cov -= U~^T U~ ----
        if (tid < NS) {
            const float* Ta = &T[tid * SRD];
            const float* Tz = &T[64 * SRD];
            float p0 = 0.f, p1 = 0.f, p2 = 0.f, p3 = 0.f;
            #pragma unroll 4
            for (int i = 0; i < 64; i += 4) {
                p0 += Ta[i] * Tz[i];     p1 += Ta[i + 1] * Tz[i + 1];
                p2 += Ta[i + 2] * Tz[i + 2]; p3 += Ta[i + 3] * Tz[i + 3];
            }
            float mn = mup[tid] + ((p0 + p1) + (p2 + p3));
            mu[tid] = mn;
            outmu[(size_t)t * BATCH * NS + b * NS + tid] = mn;
        }
        {
            float acc[4][4] = {};
            #pragma unroll 1
            for (int k0 = 0; k0 < 64; k0 += 4) {
                float4 Ar0 = *(const float4*)&T[(r0 + 0) * SRD + k0];
                float4 Ar1 = *(const float4*)&T[(r0 + 1) * SRD + k0];
                float4 Ar2 = *(const float4*)&T[(r0 + 2) * SRD + k0];
                float4 Ar3 = *(const float4*)&T[(r0 + 3) * SRD + k0];
                float4 Br0 = *(const float4*)&T[(c0 + 0) * SRD + k0];
                float4 Br1 = *(const float4*)&T[(c0 + 1) * SRD + k0];
                float4 Br2 = *(const float4*)&T[(c0 + 2) * SRD + k0];
                float4 Br3 = *(const float4*)&T[(c0 + 3) * SRD + k0];
                DOT4(acc[0][0], Ar0, Br0); DOT4(acc[0][1], Ar0, Br1); DOT4(acc[0][2], Ar0, Br2); DOT4(acc[0][3], Ar0, Br3);
                DOT4(acc[1][0], Ar1, Br0); DOT4(acc[1][1], Ar1, Br1); DOT4(acc[1][2], Ar1, Br2); DOT4(acc[1][3], Ar1, Br3);
                DOT4(acc[2][0], Ar2, Br0); DOT4(acc[2][1], Ar2, Br1); DOT4(acc[2][2], Ar2, Br2); DOT4(acc[2][3], Ar2, Br3);
                DOT4(acc[3][0], Ar3, Br0); DOT4(acc[3][1], Ar3, Br1); DOT4(acc[3][2], Ar3, Br2); DOT4(acc[3][3], Ar3, Br3);
            }
            #pragma unroll
            for (int i = 0; i < 4; ++i)
                #pragma unroll
                for (int j = 0; j < 4; ++j)
                    Mc[(r0 + i) * SRD + (c0 + j)] -= acc[i][j];
        }
        __syncthreads();

        // ---- H: state_logsigma = 0.5 * log(diag(cov_post)) ----
        if (tid < NS) {
            float cv = Mc[tid * SRD + tid];
            outls[(size_t)t * BATCH * NS + b * NS + tid] = 0.5f * logf(cv);
        }
        __syncthreads();
    }
}

extern "C" void kernel_launch(void* const* d_in, const int* in_sizes, int n_in,
                              void* d_out, int out_size) {
    const float* ext  = (const float*)d_in[0];   // (500, 512, 32)
    const float* obs  = (const float*)d_in[1];   // (500, 512, 64)
    const float* mu0  = (const float*)d_in[2];   // (512, 64)
    const float* sg0  = (const float*)d_in[3];   // (512, 64)
    const float* lsig = (const float*)d_in[4];   // (64,)
    const float* Bm   = (const float*)d_in[5];   // (64, 32)
    const float* H    = (const float*)d_in[6];   // (64, 64)
    const float* ldel = (const float*)d_in[7];   // (64,)
    float* out = (float*)d_out;                  // [mu (500,512,64) | logsigma (500,512,64)]

    const size_t SMEM = (size_t)((64 + 65 + 64) * SRD + 64 + 64 + 32 + 64 + 64) * sizeof(float);
    cudaFuncSetAttribute(akf_main, cudaFuncAttributeMaxDynamicSharedMemorySize, (int)SMEM);

    akf_prep<<<16, 256>>>(H, lsig, ldel);
    akf_main<<<BATCH, 256, SMEM>>>(ext, obs, mu0, sg0, Bm, out);
}

// round 3
// speedup vs baseline: 1.0696x; 1.0696x over previous
#include <cuda_runtime.h>
#include <math.h>

#define TSEQ 500
#define BATCH 512
#define NS 64
#define NO 64
#define NI 32

// Thread layout: tid = row*4 + q ; row in [0,64), q in [0,4).
// Thread (row,q) owns P[row][16q .. 16q+15] in registers.
// mu[row] lives in the q==0 thread's register.

__global__ void __launch_bounds__(256, 4)
akf_main(const float* __restrict__ ext, const float* __restrict__ obs,
         const float* __restrict__ mu0, const float* __restrict__ sg0,
         const float* __restrict__ lsig, const float* __restrict__ Bm,
         const float* __restrict__ Hm, const float* __restrict__ ldel,
         float* __restrict__ out)
{
    __shared__ float sh_H[64 * 64];   // H row-major (row i = h_i)
    __shared__ float sh_r[64];
    __shared__ float sh_y[64];
    __shared__ float sh_u[32];
    __shared__ float vbuf[2][64];
    __shared__ float red_s[2][8];
    __shared__ float red_i[2][8];

    const int b    = blockIdx.x;
    const int tid  = threadIdx.x;
    const int row  = tid >> 2;
    const int q    = tid & 3;
    const int c0   = q << 4;
    const int lane = tid & 31;
    const int wid  = tid >> 5;
    const bool diag_owner = ((row >> 4) == q);

    // ---- load constants ----
    for (int i = tid; i < 4096; i += 256) sh_H[i] = Hm[i];
    if (tid < 64) { float e = expf(ldel[tid]); sh_r[tid] = e * e; }

    float Breg[8];
    #pragma unroll
    for (int k = 0; k < 8; ++k) Breg[k] = Bm[row * NI + (q << 3) + k];

    float qv; { float e = expf(lsig[row]); qv = e * e; }

    // ---- init state ----
    float P[16];
    #pragma unroll
    for (int j = 0; j < 16; ++j) P[j] = 0.0f;
    float s0 = sg0[b * 64 + row];
    if (diag_owner) P[row & 15] = s0 * s0;
    float mu = mu0[b * 64 + row];          // valid in q==0 lanes

    float* outmu = out;
    float* outls = out + (size_t)TSEQ * BATCH * 64;
    if (q == 0) outmu[b * 64 + row] = mu;
    if (diag_owner) outls[b * 64 + row] = logf(s0);
    __syncthreads();

    for (int t = 1; t < TSEQ; ++t) {
        // ---- load step inputs ----
        if (tid < 64) sh_y[tid] = obs[((size_t)t * BATCH + b) * 64 + tid];
        if (tid < 32) sh_u[tid] = ext[((size_t)(t - 1) * BATCH + b) * 32 + tid];
        __syncthreads();

        // ---- predict: P += diag(q) ; mu += B u ----
        if (diag_owner) P[row & 15] += qv;
        {
            float a = 0.0f;
            #pragma unroll
            for (int k = 0; k < 8; ++k) a += Breg[k] * sh_u[(q << 3) + k];
            a += __shfl_xor_sync(0xffffffffu, a, 1);
            a += __shfl_xor_sync(0xffffffffu, a, 2);
            if (q == 0) mu += a;
        }

        // ---- 64 sequential scalar measurement updates ----
        #pragma unroll 2
        for (int i = 0; i < 64; ++i) {
            const int ib = i & 1;
            const float* h = &sh_H[i << 6];

            // v[row] partial: P strip . h strip
            float4 h0 = *(const float4*)&h[c0 + 0];
            float4 h1 = *(const float4*)&h[c0 + 4];
            float4 h2 = *(const float4*)&h[c0 + 8];
            float4 h3 = *(const float4*)&h[c0 + 12];
            float pp = P[0]  * h0.x + P[1]  * h0.y + P[2]  * h0.z + P[3]  * h0.w
                     + P[4]  * h1.x + P[5]  * h1.y + P[6]  * h1.z + P[7]  * h1.w
                     + P[8]  * h2.x + P[9]  * h2.y + P[10] * h2.z + P[11] * h2.w
                     + P[12] * h3.x + P[13] * h3.y + P[14] * h3.z + P[15] * h3.w;
            // reduce over 4 quarter-lanes -> full v[row] replicated
            pp += __shfl_xor_sync(0xffffffffu, pp, 1);
            pp += __shfl_xor_sync(0xffffffffu, pp, 2);

            // s = h^T v + r_i ; innov dot = h^T mu  (q==0 lanes contribute)
            float hr  = h[row];
            float sc  = (q == 0) ? hr * pp : 0.0f;
            float icv = (q == 0) ? hr * mu : 0.0f;
            #pragma unroll
            for (int m = 16; m > 0; m >>= 1) {
                sc  += __shfl_xor_sync(0xffffffffu, sc,  m);
                icv += __shfl_xor_sync(0xffffffffu, icv, m);
            }
            if (lane == 0) { red_s[ib][wid] = sc; red_i[ib][wid] = icv; }
            if (q == 0)    vbuf[ib][row] = pp;
            __syncthreads();

            // scalar gain pieces (redundant per thread, all smem-broadcast)
            float ssum = sh_r[i], isum = 0.0f;
            #pragma unroll
            for (int w = 0; w < 8; ++w) { ssum += red_s[ib][w]; isum += red_i[ib][w]; }
            float rs   = __fdividef(1.0f, ssum);
            float coef = (sh_y[i] - isum) * rs;
            float w0   = pp * rs;

            // rank-1 update of P strip ; mu update
            float4 v0 = *(const float4*)&vbuf[ib][c0 + 0];
            float4 v1 = *(const float4*)&vbuf[ib][c0 + 4];
            float4 v2 = *(const float4*)&vbuf[ib][c0 + 8];
            float4 v3 = *(const float4*)&vbuf[ib][c0 + 12];
            P[0]  -= w0 * v0.x;  P[1]  -= w0 * v0.y;  P[2]  -= w0 * v0.z;  P[3]  -= w0 * v0.w;
            P[4]  -= w0 * v1.x;  P[5]  -= w0 * v1.y;  P[6]  -= w0 * v1.z;  P[7]  -= w0 * v1.w;
            P[8]  -= w0 * v2.x;  P[9]  -= w0 * v2.y;  P[10] -= w0 * v2.z;  P[11] -= w0 * v2.w;
            P[12] -= w0 * v3.x;  P[13] -= w0 * v3.y;  P[14] -= w0 * v3.z;  P[15] -= w0 * v3.w;
            if (q == 0) mu += pp * coef;
        }

        // ---- outputs ----
        if (q == 0)
            outmu[((size_t)t * BATCH + b) * 64 + row] = mu;
        if (diag_owner)
            outls[((size_t)t * BATCH + b) * 64 + row] = 0.5f * logf(P[row & 15]);
        __syncthreads();   // protect sh_y/sh_u for next step
    }
}

extern "C" void kernel_launch(void* const* d_in, const int* in_sizes, int n_in,
                              void* d_out, int out_size) {
    const float* ext  = (const float*)d_in[0];   // (500, 512, 32)
    const float* obs  = (const float*)d_in[1];   // (500, 512, 64)
    const float* mu0  = (const float*)d_in[2];   // (512, 64)
    const float* sg0  = (const float*)d_in[3];   // (512, 64)
    const float* lsig = (const float*)d_in[4];   // (64,)
    const float* Bm   = (const float*)d_in[5];   // (64, 32)
    const float* H    = (const float*)d_in[6];   // (64, 64)
    const float* ldel = (const float*)d_in[7];   // (64,)
    float* out = (float*)d_out;

    akf_main<<<BATCH, 256>>>(ext, obs, mu0, sg0, lsig, Bm, H, ldel, out);
}